// round 10
// baseline (speedup 1.0000x reference)
#include <cuda_runtime.h>
#include <cuda_bf16.h>
#include <float.h>
#include <stdint.h>

#define Bsz 16
#define Npt 4096
#define Cft 64
#define Mc  1024
#define Kn  64
#define Hd  128
#define CIN 67

__device__ int   g_idx[Bsz*Mc];
__device__ int   g_prog[Bsz];
__device__ int   g_work;
__device__ float g_poss_dump[Bsz*Mc*3];

// ---------------- acquire/release helpers ---------------------------------
__device__ __forceinline__ int ld_acq(const int* p) {
    int v;
    asm volatile("ld.acquire.gpu.global.b32 %0, [%1];" : "=r"(v) : "l"(p));
    return v;
}
__device__ __forceinline__ void st_rel(int* p, int v) {
    asm volatile("st.release.gpu.global.b32 [%0], %1;" :: "l"(p), "r"(v));
}

// ---------------- MLP helpers (unchanged from R9) --------------------------
#define PITCH 272
#define OFF_W1H 0
#define OFF_W1L 21760
#define OFF_W2H 43520
#define OFF_W2L 78336
#define OFF_FH  113152
#define OFF_FL  147968
#define OFF_B1  182784
#define OFF_B2  183296
#define OFF_WMX 183808
#define MLP_SMEM 187904

__device__ __forceinline__ uint32_t smem_u32(const void* p) {
    uint32_t a;
    asm("{ .reg .u64 t; cvta.to.shared.u64 t, %1; cvt.u32.u64 %0, t; }"
        : "=r"(a) : "l"(p));
    return a;
}
__device__ __forceinline__ void ldsm_x4(uint32_t addr, uint32_t* r) {
    asm volatile("ldmatrix.sync.aligned.m8n8.x4.shared.b16 {%0,%1,%2,%3}, [%4];"
        : "=r"(r[0]), "=r"(r[1]), "=r"(r[2]), "=r"(r[3]) : "r"(addr));
}
__device__ __forceinline__ void ldsm_x4t(uint32_t addr, uint32_t* r) {
    asm volatile("ldmatrix.sync.aligned.m8n8.x4.trans.shared.b16 {%0,%1,%2,%3}, [%4];"
        : "=r"(r[0]), "=r"(r[1]), "=r"(r[2]), "=r"(r[3]) : "r"(addr));
}
__device__ __forceinline__ void mma16816(float* d, const uint32_t* a, const uint32_t* b) {
    asm volatile("mma.sync.aligned.m16n8k16.row.col.f32.bf16.bf16.f32 "
        "{%0,%1,%2,%3}, {%4,%5,%6,%7}, {%8,%9}, {%0,%1,%2,%3};"
        : "+f"(d[0]), "+f"(d[1]), "+f"(d[2]), "+f"(d[3])
        : "r"(a[0]), "r"(a[1]), "r"(a[2]), "r"(a[3]), "r"(b[0]), "r"(b[1]));
}
__device__ __forceinline__ void pack_hilo(float v0, float v1, uint32_t& hi, uint32_t& lo) {
    __nv_bfloat16 h0 = __float2bfloat16(v0), h1 = __float2bfloat16(v1);
    __nv_bfloat162 hh; hh.x = h0; hh.y = h1;
    hi = *(uint32_t*)&hh;
    __nv_bfloat162 gg;
    gg.x = __float2bfloat16(v0 - __bfloat162float(h0));
    gg.y = __float2bfloat16(v1 - __bfloat162float(h1));
    lo = *(uint32_t*)&gg;
}

template <int KSTEPS>
__device__ __forceinline__ void do_layer(char* sm, int offAh, int offAl,
                                         int offBh, int offBl,
                                         int wrow0, int lane, float d[16][4]) {
    uint32_t aHi = smem_u32(sm + offAh) + (uint32_t)(wrow0 + (lane & 15)) * PITCH
                   + ((lane >> 4) << 4);
    uint32_t aLo = smem_u32(sm + offAl) + (uint32_t)(wrow0 + (lane & 15)) * PITCH
                   + ((lane >> 4) << 4);
    uint32_t bprow = (uint32_t)((lane & 7) + ((lane >> 3) & 1) * 8) * PITCH
                     + (uint32_t)((lane >> 4) << 4);
    uint32_t bHi0 = smem_u32(sm + offBh) + bprow;
    uint32_t bLo0 = smem_u32(sm + offBl) + bprow;
#pragma unroll
    for (int ks = 0; ks < KSTEPS; ks++) {
        uint32_t ah[4], al[4];
        ldsm_x4(aHi + ks * 32, ah);
        ldsm_x4(aLo + ks * 32, al);
        uint32_t bh_b = bHi0 + (uint32_t)ks * 16 * PITCH;
        uint32_t bl_b = bLo0 + (uint32_t)ks * 16 * PITCH;
#pragma unroll
        for (int ntp = 0; ntp < 8; ntp++) {
            uint32_t bh[4], bl[4];
            ldsm_x4t(bh_b + ntp * 32, bh);
            ldsm_x4t(bl_b + ntp * 32, bl);
            mma16816(d[2*ntp],     ah, bh);
            mma16816(d[2*ntp],     ah, bl);
            mma16816(d[2*ntp],     al, bh);
            mma16816(d[2*ntp + 1], ah, bh + 2);
            mma16816(d[2*ntp + 1], ah, bl + 2);
            mma16816(d[2*ntp + 1], al, bh + 2);
        }
    }
}

// ---------------- FPS producer (256 thr x 16 pts; picks bit-identical) ----
#define FPS_T 256
#define FPPT 16

__device__ void fps_part(const float* __restrict__ pos, char* dynsm) {
    float* spx = (float*)dynsm;
    float* spy = spx + Npt;
    float* spz = spy + Npt;
    __shared__ unsigned swv[2][8];
    __shared__ unsigned swc[2][8];

    int b = blockIdx.x;
    const float* p = pos + b * Npt * 3;
    int t = threadIdx.x, lane = t & 31, w = t >> 5;

    float px[FPPT], py[FPPT], pz[FPPT], dd[FPPT];
#pragma unroll
    for (int j = 0; j < FPPT; j++) {
        int i = t + j * FPS_T;
        float xx = p[i*3+0], yy = p[i*3+1], zz = p[i*3+2];
        px[j] = xx; py[j] = yy; pz[j] = zz;
        spx[i] = xx; spy[i] = yy; spz[i] = zz;
        dd[j] = FLT_MAX;
    }
    if (t == 0) { g_idx[b * Mc] = 0; st_rel(&g_prog[b], 1); }
    __syncthreads();

    int last = 0, par = 0;
    for (int s = 1; s < Mc; s++) {
        float lx = spx[last], ly = spy[last], lz = spz[last];
        unsigned vmx = 0u;
#pragma unroll
        for (int j = 0; j < FPPT; j++) {
            float dx = __fsub_rn(px[j], lx);
            float dy = __fsub_rn(py[j], ly);
            float dz = __fsub_rn(pz[j], lz);
            float d  = __fadd_rn(__fadd_rn(__fmul_rn(dx,dx), __fmul_rn(dy,dy)),
                                 __fmul_rn(dz,dz));
            float v = fminf(dd[j], d);
            dd[j] = v;
            unsigned vu = __float_as_uint(v);
            vmx = vmx > vu ? vmx : vu;
        }
        unsigned cand = 0x7fffffffu;
#pragma unroll
        for (int j = FPPT - 1; j >= 0; j--)
            if (__float_as_uint(dd[j]) == vmx) cand = (unsigned)(t + j * FPS_T);
        unsigned wmax = __reduce_max_sync(0xffffffffu, vmx);
        unsigned csel = (vmx == wmax) ? cand : 0x7fffffffu;
        unsigned wcnd = __reduce_min_sync(0xffffffffu, csel);
        if (lane == 0) { swv[par][w] = wmax; swc[par][w] = wcnd; }
        __syncthreads();
        unsigned vv = (lane < 8) ? swv[par][lane] : 0u;
        unsigned cc = (lane < 8) ? swc[par][lane] : 0x7fffffffu;
        unsigned vm  = __reduce_max_sync(0xffffffffu, vv);
        unsigned cmn = __reduce_min_sync(0xffffffffu, (vv == vm) ? cc : 0x7fffffffu);
        last = (int)cmn;
        par ^= 1;
        if (t == 0) { g_idx[b * Mc + s] = last; st_rel(&g_prog[b], s + 1); }
    }
}

// ---------------- fused kernel --------------------------------------------
extern __shared__ __align__(128) char mlps[];

__global__ __launch_bounds__(256, 1) void fused_kernel(
    const float* __restrict__ x, const float* __restrict__ pos,
    const float* __restrict__ W1, const float* __restrict__ b1,
    const float* __restrict__ W2, const float* __restrict__ b2,
    float* __restrict__ out, float* __restrict__ poss) {
    char* sm = mlps;
    float* b1s = (float*)(sm + OFF_B1);
    float* b2s = (float*)(sm + OFF_B2);
    float* wmx = (float*)(sm + OFF_WMX);

    int tid = threadIdx.x, lane = tid & 31, warp = tid >> 5;
    int wrow0 = warp * 16;

    // producer phase for blocks 0..15
    if (blockIdx.x < Bsz) fps_part(pos, sm);
    __syncthreads();

    // stage weights hi/lo into [k][n] pitch-136 layout (once)
    for (int i = tid; i < 80 * 128; i += 256) {
        int kk = i >> 7, n = i & 127;
        float v = (kk < CIN) ? W1[kk * Hd + n] : 0.f;
        __nv_bfloat16 hv = __float2bfloat16(v);
        *(__nv_bfloat16*)(sm + OFF_W1H + kk * PITCH + n * 2) = hv;
        *(__nv_bfloat16*)(sm + OFF_W1L + kk * PITCH + n * 2) =
            __float2bfloat16(v - __bfloat162float(hv));
    }
    for (int i = tid; i < 128 * 128; i += 256) {
        int kk = i >> 7, n = i & 127;
        float v = W2[kk * Hd + n];
        __nv_bfloat16 hv = __float2bfloat16(v);
        *(__nv_bfloat16*)(sm + OFF_W2H + kk * PITCH + n * 2) = hv;
        *(__nv_bfloat16*)(sm + OFF_W2L + kk * PITCH + n * 2) =
            __float2bfloat16(v - __bfloat162float(hv));
    }
    if (tid < Hd) { b1s[tid] = b1[tid]; b2s[tid] = b2[tid]; }

    __shared__ int   s_w;
    __shared__ int   snbr[2][Kn];
    __shared__ int   scnt[2];
    __shared__ float sctr[2][3];

    while (true) {
        if (tid == 0) s_w = atomicAdd(&g_work, 1);
        __syncthreads();   // also protects wmx/feat reuse across iterations
        int wk = s_w;
        if (wk >= Bsz * Mc / 2) break;
        int b  = wk & (Bsz - 1);
        int pp = wk >> 4;
        int bc = (b << 10) + (pp << 1);

        // wait for FPS producer of batch b
        if (tid == 0) {
            int need = (pp << 1) + 2;
            while (ld_acq(&g_prog[b]) < need) __nanosleep(128);
        }
        __syncthreads();

        // ---- inline radius query (warps 0/1, one center each) ----------
        if (warp < 2) {
            int cm = bc + warp;
            int ci = g_idx[cm];
            const float* p2 = pos + b * Npt * 3;
            float sx = p2[ci*3+0], sy = p2[ci*3+1], sz = p2[ci*3+2];
            if (lane == 0) {
                poss[cm*3+0] = sx; poss[cm*3+1] = sy; poss[cm*3+2] = sz;
                sctr[warp][0] = sx; sctr[warp][1] = sy; sctr[warp][2] = sz;
            }
            float sn = __fadd_rn(__fadd_rn(__fmul_rn(sx,sx), __fmul_rn(sy,sy)),
                                 __fmul_rn(sz,sz));
            const float R2 = 0.2f * 0.2f;
            int cnt = 0;
            for (int base = 0; base < Npt; base += 32) {
                int   i = base + lane;
                float xx = p2[i*3+0], yy = p2[i*3+1], zz = p2[i*3+2];
                float pn = __fadd_rn(__fadd_rn(__fmul_rn(xx,xx), __fmul_rn(yy,yy)),
                                     __fmul_rn(zz,zz));
                float dot = __fadd_rn(__fadd_rn(__fmul_rn(sx,xx), __fmul_rn(sy,yy)),
                                      __fmul_rn(sz,zz));
                float d2 = __fsub_rn(__fadd_rn(sn, pn), __fmul_rn(2.0f, dot));
                bool  in = (d2 <= R2);
                unsigned ball = __ballot_sync(0xffffffffu, in);
                if (in) {
                    int ppos = cnt + __popc(ball & ((1u << lane) - 1u));
                    if (ppos < Kn) snbr[warp][ppos] = i;
                }
                cnt += __popc(ball);
                if (cnt >= Kn) break;
            }
            if (cnt > Kn) cnt = Kn;
            for (int k2 = cnt + lane; k2 < Kn; k2 += 32) snbr[warp][k2] = 0;
            if (lane == 0) scnt[warp] = cnt;
        }
        __syncthreads();

        // ---- gather (rows warp-local) -----------------------------------
        {
            int r = tid >> 1, h = tid & 1;
            int c = r >> 6;
            int k = r & 63;
            int nb = snbr[c][k];
            const float* xr = x + ((size_t)b * Npt + nb) * Cft + h * 32;
            char* fh = sm + OFF_FH + r * PITCH + h * 64;
            char* fl = sm + OFF_FL + r * PITCH + h * 64;
#pragma unroll
            for (int j = 0; j < 8; j++) {
                float4 v = *(const float4*)(xr + j * 4);
                uint32_t h0, l0, h1v, l1v;
                pack_hilo(v.x, v.y, h0, l0);
                pack_hilo(v.z, v.w, h1v, l1v);
                *(uint32_t*)(fh + j * 8)     = h0;
                *(uint32_t*)(fh + j * 8 + 4) = h1v;
                *(uint32_t*)(fl + j * 8)     = l0;
                *(uint32_t*)(fl + j * 8 + 4) = l1v;
            }
            if (h == 0) {
                const float* pb = pos + b * Npt * 3;
                float pd0 = pb[nb*3+0] - sctr[c][0];
                float pd1 = pb[nb*3+1] - sctr[c][1];
                float pd2 = pb[nb*3+2] - sctr[c][2];
                char* fh2 = sm + OFF_FH + r * PITCH + 128;
                char* fl2 = sm + OFF_FL + r * PITCH + 128;
                uint32_t h0, l0, h1v, l1v;
                pack_hilo(pd0, pd1, h0, l0);
                pack_hilo(pd2, 0.f, h1v, l1v);
                *(uint32_t*)(fh2)     = h0;  *(uint32_t*)(fh2 + 4) = h1v;
                *(uint32_t*)(fl2)     = l0;  *(uint32_t*)(fl2 + 4) = l1v;
#pragma unroll
                for (int j = 2; j < 8; j++) {
                    *(uint32_t*)(fh2 + j * 4) = 0u;
                    *(uint32_t*)(fl2 + j * 4) = 0u;
                }
            }
        }
        __syncwarp();

        // ---- layer 1 (K=80) ---------------------------------------------
        float d[16][4];
#pragma unroll
        for (int nt = 0; nt < 16; nt++)
#pragma unroll
            for (int q = 0; q < 4; q++) d[nt][q] = 0.f;
        do_layer<5>(sm, OFF_FH, OFF_FL, OFF_W1H, OFF_W1L, wrow0, lane, d);

        // ---- epilogue 1 ---------------------------------------------------
        {
            int r0 = wrow0 + (lane >> 2);
#pragma unroll
            for (int nt = 0; nt < 16; nt++) {
                int c0 = nt * 8 + (lane & 3) * 2;
                float v00 = fmaxf(d[nt][0] + b1s[c0],     0.f);
                float v01 = fmaxf(d[nt][1] + b1s[c0 + 1], 0.f);
                float v10 = fmaxf(d[nt][2] + b1s[c0],     0.f);
                float v11 = fmaxf(d[nt][3] + b1s[c0 + 1], 0.f);
                uint32_t h0, l0, h1v, l1v;
                pack_hilo(v00, v01, h0, l0);
                pack_hilo(v10, v11, h1v, l1v);
                *(uint32_t*)(sm + OFF_FH + r0 * PITCH + c0 * 2)       = h0;
                *(uint32_t*)(sm + OFF_FL + r0 * PITCH + c0 * 2)       = l0;
                *(uint32_t*)(sm + OFF_FH + (r0 + 8) * PITCH + c0 * 2) = h1v;
                *(uint32_t*)(sm + OFF_FL + (r0 + 8) * PITCH + c0 * 2) = l1v;
            }
        }
        __syncwarp();

        // ---- layer 2 (K=128) ----------------------------------------------
#pragma unroll
        for (int nt = 0; nt < 16; nt++)
#pragma unroll
            for (int q = 0; q < 4; q++) d[nt][q] = 0.f;
        do_layer<8>(sm, OFF_FH, OFF_FL, OFF_W2H, OFF_W2L, wrow0, lane, d);

        // ---- epilogue 2 ----------------------------------------------------
        {
            int cnt_w = scnt[warp >> 2];
            int k0 = (wrow0 & 63) + (lane >> 2);
            bool va = k0 < cnt_w, vb = (k0 + 8) < cnt_w;
#pragma unroll
            for (int nt = 0; nt < 16; nt++) {
                int c0 = nt * 8 + (lane & 3) * 2;
                float m0 = fmaxf(va ? fmaxf(d[nt][0] + b2s[c0], 0.f) : 0.f,
                                 vb ? fmaxf(d[nt][2] + b2s[c0], 0.f) : 0.f);
                float m1 = fmaxf(va ? fmaxf(d[nt][1] + b2s[c0 + 1], 0.f) : 0.f,
                                 vb ? fmaxf(d[nt][3] + b2s[c0 + 1], 0.f) : 0.f);
#pragma unroll
                for (int o = 4; o <= 16; o <<= 1) {
                    m0 = fmaxf(m0, __shfl_xor_sync(0xffffffffu, m0, o));
                    m1 = fmaxf(m1, __shfl_xor_sync(0xffffffffu, m1, o));
                }
                if (lane < 4) {
                    wmx[warp * 128 + c0]     = m0;
                    wmx[warp * 128 + c0 + 1] = m1;
                }
            }
        }
        __syncthreads();
        {
            int col = tid & 127, ctr = tid >> 7;
            float mv = fmaxf(
                fmaxf(wmx[(ctr * 4 + 0) * 128 + col], wmx[(ctr * 4 + 1) * 128 + col]),
                fmaxf(wmx[(ctr * 4 + 2) * 128 + col], wmx[(ctr * 4 + 3) * 128 + col]));
            int cmo = bc + ctr;
            out[(size_t)cmo * Hd + col] = (scnt[ctr] > 0) ? mv : 0.f;
        }
    }
}

__global__ void init_kernel() {
    if (threadIdx.x < Bsz) g_prog[threadIdx.x] = 0;
    if (threadIdx.x == 0) g_work = 0;
}

// ============================ launch ======================================
extern "C" void kernel_launch(void* const* d_in, const int* in_sizes, int n_in,
                              void* d_out, int out_size) {
    const float* x   = (const float*)d_in[0];
    const float* pos = (const float*)d_in[1];
    const float* W1  = (const float*)d_in[2];
    const float* b1  = (const float*)d_in[3];
    const float* W2  = (const float*)d_in[4];
    const float* b2  = (const float*)d_in[5];
    float* out = (float*)d_out;

    float* poss;
    if (out_size >= Bsz * Mc * (Hd + 3)) {
        poss = out + (size_t)Bsz * Mc * Hd;
    } else {
        void* tmp = nullptr;
        cudaGetSymbolAddress(&tmp, g_poss_dump);
        poss = (float*)tmp;
    }

    cudaFuncSetAttribute(fused_kernel, cudaFuncAttributeMaxDynamicSharedMemorySize,
                         MLP_SMEM);

    init_kernel<<<1, 32>>>();
    fused_kernel<<<152, 256, MLP_SMEM>>>(x, pos, W1, b1, W2, b2, out, poss);
}